// round 13
// baseline (speedup 1.0000x reference)
#include <cuda_runtime.h>
#include <cuda_fp16.h>
#include <math.h>
#include <stdint.h>

typedef __half fp16;

#define T_TOKENS 8192
#define D_DIM    1024
#define E_EXP    8
#define I_DIM    938
#define GU_DIM   1876
#define GUP      1920      // 2I padded (15*128)
#define IP       960       // I padded (15*64)
#define NSLOT    9         // slot0 = shared, 1..8 = routed

#define BM 128
#define BN 128
#define BK 64
#define NTHR 512                        // 16 warps, 4x4 grid of 32x32 warp tiles
#define SROW 144                        // 64 fp16 = 128B data + 16B pad
#define OFF_A 0
#define OFF_B (BM*SROW)                 // 18432
#define STAGEB ((BM+BN)*SROW)           // 36864
#define NSTAGE 3
#define SMEM_DYN (1024 + NSTAGE*STAGEB) // 111616

// ---------------- static scratch ----------------
__device__ int    g_cnt[E_EXP];          // ZERO at load; combine restores zero each call
__device__ int    g_tok[E_EXP * T_TOKENS];
__device__ int4   g_tk2[T_TOKENS];
__device__ float2 g_w2 [T_TOKENS];
__device__ fp16   g_x16[T_TOKENS * D_DIM];
__device__ fp16   g_wgu[NSLOT * GUP * D_DIM];     // interleaved (gate_i, up_i) rows
__device__ fp16   g_wdn[NSLOT * D_DIM * IP];
__device__ fp16   g_act[(size_t)NSLOT * T_TOKENS * IP];
__device__ fp16   g_ybuf[(size_t)E_EXP * T_TOKENS * D_DIM];

// ---------------- helpers ----------------
__device__ __forceinline__ uint32_t smem_u32(const void* p) {
    uint32_t a;
    asm("{ .reg .u64 t; cvta.to.shared.u64 t, %1; cvt.u32.u64 %0, t; }" : "=r"(a) : "l"(p));
    return a;
}
__device__ __forceinline__ void cp16(uint32_t s, const void* g) {
    asm volatile("cp.async.cg.shared.global [%0], [%1], 16;" :: "r"(s), "l"(g));
}
__device__ __forceinline__ void ldsm4(uint32_t* r, uint32_t a) {
    asm volatile("ldmatrix.sync.aligned.m8n8.x4.shared.b16 {%0,%1,%2,%3}, [%4];"
        : "=r"(r[0]), "=r"(r[1]), "=r"(r[2]), "=r"(r[3]) : "r"(a));
}
// fp16-accumulator HMMA (the rate experiment)
__device__ __forceinline__ void mma16816h(uint32_t* d, const uint32_t* a, const uint32_t* b) {
    asm volatile(
        "mma.sync.aligned.m16n8k16.row.col.f16.f16.f16.f16 "
        "{%0,%1}, {%2,%3,%4,%5}, {%6,%7}, {%0,%1};"
        : "+r"(d[0]), "+r"(d[1])
        : "r"(a[0]), "r"(a[1]), "r"(a[2]), "r"(a[3]), "r"(b[0]), "r"(b[1]));
}

// -- mainloop: 128x128 CTA tile, 32x32 warp tile (4x4, 512 thr), fp16-acc + fp32 drain --
__device__ __forceinline__ void gemm_mainloop(
    uint32_t s0,
    const fp16* sa,                       // per-thread A row ptr (row = tid>>2)
    const fp16* sb,                       // per-thread B row ptr (row = tid>>2)
    int NC, int tid, float acc[2][4][4])
{
    const int lane = tid & 31, wid = tid >> 5;
    const uint32_t rowoff = (uint32_t)(tid >> 2) * SROW + (uint32_t)(tid & 3) * 32;
    const int kel = (tid & 3) * 16;

#define LOAD_STAGE(st, c) do {                                              \
        uint32_t base_ = s0 + (st) * STAGEB;                                \
        int k0_ = (c) * BK + kel;                                           \
        _Pragma("unroll")                                                   \
        for (int j = 0; j < 2; j++) {                                       \
            cp16(base_ + OFF_A + rowoff + j*16, sa + k0_ + j*8);            \
            cp16(base_ + OFF_B + rowoff + j*16, sb + k0_ + j*8);            \
        }                                                                   \
        asm volatile("cp.async.commit_group;" ::: "memory");                \
    } while (0)

    LOAD_STAGE(0, 0);
    LOAD_STAGE(1, 1);    // NC >= 2 always (min NC = 15)

    const int mwb = (wid >> 2) * 32;
    const int nwb = (wid & 3) * 32;
    const int arow   = mwb + (lane & 15);
    const int acolB0 = (lane >> 4) * 16;
    const int bnrow  = nwb + ((lane >> 4) * 8) + (lane & 7);
    const int bkB0   = ((lane >> 3) & 1) * 16;

    uint32_t acc16[2][4][2];
#pragma unroll
    for (int mi = 0; mi < 2; mi++)
#pragma unroll
        for (int j = 0; j < 4; j++) { acc16[mi][j][0] = 0u; acc16[mi][j][1] = 0u; }

#define DRAIN() do {                                                        \
        _Pragma("unroll")                                                   \
        for (int mi = 0; mi < 2; mi++)                                      \
        _Pragma("unroll")                                                   \
        for (int j = 0; j < 4; j++) {                                       \
            float2 lo = __half22float2(*(__half2*)&acc16[mi][j][0]);        \
            float2 hi = __half22float2(*(__half2*)&acc16[mi][j][1]);        \
            acc[mi][j][0] += lo.x; acc[mi][j][1] += lo.y;                   \
            acc[mi][j][2] += hi.x; acc[mi][j][3] += hi.y;                   \
            acc16[mi][j][0] = 0u;  acc16[mi][j][1] = 0u;                    \
        }                                                                   \
    } while (0)

    int st = 0;
    for (int c = 0; c < NC; c++) {
        if (c + 1 < NC) asm volatile("cp.async.wait_group 1;" ::: "memory");
        else            asm volatile("cp.async.wait_group 0;" ::: "memory");
        __syncthreads();
        if (c + 2 < NC) {
            int ls = st + 2; if (ls >= NSTAGE) ls -= NSTAGE;
            LOAD_STAGE(ls, c + 2);
        }
        const uint32_t tb = s0 + st * STAGEB;
#pragma unroll
        for (int ks = 0; ks < 4; ks++) {
            const uint32_t acolB = ks * 32 + acolB0;
            const uint32_t bcolB = ks * 32 + bkB0;
            uint32_t ah[2][4];
#pragma unroll
            for (int mi = 0; mi < 2; mi++)
                ldsm4(ah[mi], tb + OFF_A + (uint32_t)(arow + mi * 16) * SROW + acolB);
#pragma unroll
            for (int nb = 0; nb < 2; nb++) {
                uint32_t bh[4];
                ldsm4(bh, tb + OFF_B + (uint32_t)(bnrow + nb * 16) * SROW + bcolB);
#pragma unroll
                for (int mi = 0; mi < 2; mi++) {
                    mma16816h(acc16[mi][nb * 2 + 0], ah[mi], bh + 0);
                    mma16816h(acc16[mi][nb * 2 + 1], ah[mi], bh + 2);
                }
            }
            if (ks & 1) DRAIN();    // fp32 drain every K=32
        }
        st++; if (st == NSTAGE) st = 0;
    }
#undef DRAIN
#undef LOAD_STAGE
}

// ---------------- GEMM1: H = X @ Wgu^T, fused swiglu -> act fp16 ----------------
__global__ void __launch_bounds__(NTHR, 1) gemm1_kernel() {
    extern __shared__ char smem[];
    int* rowids = (int*)smem;
    const uint32_t s0 = smem_u32(smem) + 1024;
    const int tid = threadIdx.x;
    const int s = blockIdx.z, m0 = blockIdx.y * BM, n0 = blockIdx.x * BN;
    const int M = (s == 0) ? T_TOKENS : g_cnt[s - 1];
    if (m0 >= M) return;

    if (tid < BM) {
        int am = m0 + tid;
        int r;
        if (s == 0) r = (am < M ? am : M - 1);
        else        r = g_tok[(s - 1) * T_TOKENS + (am < M ? am : M - 1)];
        rowids[tid] = r;
    }
    __syncthreads();

    const fp16* sa = g_x16 + (long long)rowids[tid >> 2] * D_DIM;
    const fp16* sb = g_wgu + ((long long)s * GUP + n0 + (tid >> 2)) * D_DIM;

    float acc[2][4][4];
#pragma unroll
    for (int i = 0; i < 2; i++)
#pragma unroll
        for (int j = 0; j < 4; j++)
#pragma unroll
            for (int k = 0; k < 4; k++) acc[i][j][k] = 0.f;

    gemm_mainloop(s0, sa, sb, D_DIM / BK, tid, acc);

    const int lane = tid & 31, wid = tid >> 5;
    const int mwb = (wid >> 2) * 32, nwb = (wid & 3) * 32;
    fp16* oa = g_act + (size_t)s * T_TOKENS * IP;
#pragma unroll
    for (int mi = 0; mi < 2; mi++) {
        const int r0 = m0 + mwb + mi * 16 + (lane >> 2);
#pragma unroll
        for (int j = 0; j < 4; j++) {
            const int nbase = n0 + nwb + j * 8 + (lane & 3) * 2;
            const int acol = nbase >> 1;
            const float* a = acc[mi][j];
            if (r0 < M) {
                float g = a[0], u = a[1];
                float v = (g / (1.f + __expf(-g))) * u;
                oa[(size_t)r0 * IP + acol] = __float2half(v);
            }
            if (r0 + 8 < M) {
                float g = a[2], u = a[3];
                float v = (g / (1.f + __expf(-g))) * u;
                oa[(size_t)(r0 + 8) * IP + acol] = __float2half(v);
            }
        }
    }
}

// ---------------- GEMM2: C = act @ down^T (slot0 -> out fp32, 1..8 -> ybuf fp16) ------
__global__ void __launch_bounds__(NTHR, 1) gemm2_kernel(float* __restrict__ out) {
    extern __shared__ char smem[];
    const uint32_t s0 = smem_u32(smem) + 1024;
    const int tid = threadIdx.x;
    const int s = blockIdx.z, m0 = blockIdx.y * BM, n0 = blockIdx.x * BN;
    const int M = (s == 0) ? T_TOKENS : g_cnt[s - 1];
    if (m0 >= M) return;

    const int amr = m0 + (tid >> 2) < T_TOKENS ? m0 + (tid >> 2) : T_TOKENS - 1;
    const fp16* sa = g_act + (size_t)s * T_TOKENS * IP + (size_t)amr * IP;
    const fp16* sb = g_wdn + ((long long)s * D_DIM + n0 + (tid >> 2)) * IP;

    float acc[2][4][4];
#pragma unroll
    for (int i = 0; i < 2; i++)
#pragma unroll
        for (int j = 0; j < 4; j++)
#pragma unroll
            for (int k = 0; k < 4; k++) acc[i][j][k] = 0.f;

    gemm_mainloop(s0, sa, sb, IP / BK, tid, acc);

    const int lane = tid & 31, wid = tid >> 5;
    const int mwb = (wid >> 2) * 32, nwb = (wid & 3) * 32;
    if (s == 0) {
#pragma unroll
        for (int mi = 0; mi < 2; mi++) {
            const int r0 = m0 + mwb + mi * 16 + (lane >> 2);
#pragma unroll
            for (int j = 0; j < 4; j++) {
                const int n = n0 + nwb + j * 8 + (lane & 3) * 2;
                const float* a = acc[mi][j];
                if (r0 < M)     *(float2*)(out + (size_t)r0 * D_DIM + n)       = make_float2(a[0], a[1]);
                if (r0 + 8 < M) *(float2*)(out + (size_t)(r0 + 8) * D_DIM + n) = make_float2(a[2], a[3]);
            }
        }
    } else {
        fp16* C = g_ybuf + (size_t)(s - 1) * T_TOKENS * D_DIM;
#pragma unroll
        for (int mi = 0; mi < 2; mi++) {
            const int r0 = m0 + mwb + mi * 16 + (lane >> 2);
#pragma unroll
            for (int j = 0; j < 4; j++) {
                const int n = n0 + nwb + j * 8 + (lane & 3) * 2;
                const float* a = acc[mi][j];
                if (r0 < M) {
                    __align__(4) fp16 h[2] = {__float2half(a[0]), __float2half(a[1])};
                    *(uint32_t*)(C + (size_t)r0 * D_DIM + n) = *(const uint32_t*)h;
                }
                if (r0 + 8 < M) {
                    __align__(4) fp16 h[2] = {__float2half(a[2]), __float2half(a[3])};
                    *(uint32_t*)(C + (size_t)(r0 + 8) * D_DIM + n) = *(const uint32_t*)h;
                }
            }
        }
    }
}

// ------- combine: out[t] += w1*y[e1][p1] + w2*y[e2][p2]; also re-zero g_cnt ----------
__global__ void combine_kernel(float* __restrict__ out) {
    if (blockIdx.x == 0 && threadIdx.x < E_EXP) g_cnt[threadIdx.x] = 0;
    const int t = blockIdx.x;
    const int c = threadIdx.x;
    const int4 e = g_tk2[t];
    const float2 w = g_w2[t];
    const uint2* y1 = (const uint2*)(g_ybuf + ((size_t)e.x * T_TOKENS + e.y) * D_DIM);
    const uint2* y2 = (const uint2*)(g_ybuf + ((size_t)e.z * T_TOKENS + e.w) * D_DIM);
    float4* o = (float4*)(out + (size_t)t * D_DIM);
    uint2 p1 = y1[c], p2 = y2[c];
    float2 a1 = __half22float2(*(const __half2*)&p1.x);
    float2 b1 = __half22float2(*(const __half2*)&p1.y);
    float2 a2 = __half22float2(*(const __half2*)&p2.x);
    float2 b2 = __half22float2(*(const __half2*)&p2.y);
    float4 a = o[c];
    a.x += w.x * a1.x + w.y * a2.x;
    a.y += w.x * a1.y + w.y * a2.y;
    a.z += w.x * b1.x + w.y * b2.x;
    a.w += w.x * b1.y + w.y * b2.y;
    o[c] = a;
}

// ---- fused setup: cvt_x + repack wgu/wdn + router, one grid ----
#define NA_BLOCKS (T_TOKENS * D_DIM / 1024)          // 8192
#define RW_BLOCKS ((GUP + D_DIM) * NSLOT)            // 26496
#define RT_BLOCKS (T_TOKENS / 8)                     // 1024
__global__ void setup_kernel(const float* __restrict__ x, fp16* __restrict__ xo,
                             const float* __restrict__ gw,
                             const float* __restrict__ sgu, const float* __restrict__ egu,
                             const float* __restrict__ sdn, const float* __restrict__ edn,
                             fp16* __restrict__ wgu, fp16* __restrict__ wdn,
                             int* __restrict__ cnt, int* __restrict__ tok,
                             int4* __restrict__ tk2, float2* __restrict__ w2) {
    __shared__ float sgw[E_EXP * D_DIM];   // router blocks only
    const int bid = blockIdx.x;
    const int tid = threadIdx.x;

    if (bid < NA_BLOCKS) {
        const int i4 = (bid * 256 + tid) * 4;
        float4 v = *(const float4*)(x + i4);
        __align__(8) fp16 h[4];
        h[0] = __float2half(v.x); h[1] = __float2half(v.y);
        h[2] = __float2half(v.z); h[3] = __float2half(v.w);
        *(uint2*)(xo + i4) = *(const uint2*)h;
        return;
    }
    if (bid < NA_BLOCKS + RW_BLOCKS) {
        const int bid2 = bid - NA_BLOCKS;
        const int s = bid2 / (GUP + D_DIM);
        const int rr = bid2 - s * (GUP + D_DIM);
        if (rr < GUP) {
            const int r = rr;
            const int k4 = tid * 4;
            const size_t dst = ((size_t)s * GUP + r) * D_DIM + k4;
            float4 v = make_float4(0.f, 0.f, 0.f, 0.f);
            if (r < GU_DIM) {
                const int sr = (r & 1) ? (r >> 1) + I_DIM : (r >> 1);
                const float* src = (s == 0) ? (sgu + (size_t)sr * D_DIM)
                                            : (egu + ((size_t)(s - 1) * GU_DIM + sr) * D_DIM);
                v = *(const float4*)(src + k4);
            }
            __align__(8) fp16 h[4];
            h[0] = __float2half(v.x); h[1] = __float2half(v.y);
            h[2] = __float2half(v.z); h[3] = __float2half(v.w);
            *(uint2*)(wgu + dst) = *(const uint2*)h;
        } else {
            if (tid >= 240) return;
            const int n = rr - GUP;
            const int k4 = tid * 4;
            const size_t dst = ((size_t)s * D_DIM + n) * IP + k4;
            const float* src = (s == 0) ? (sdn + (size_t)n * I_DIM)
                                        : (edn + ((size_t)(s - 1) * D_DIM + n) * I_DIM);
            __align__(8) fp16 h[4];
#pragma unroll
            for (int q = 0; q < 4; q++) {
                const int i = k4 + q;
                float v = (i < I_DIM) ? __ldg(src + i) : 0.f;
                h[q] = __float2half(v);
            }
            *(uint2*)(wdn + dst) = *(const uint2*)h;
        }
        return;
    }

    // ---- router: fp32, bit-identical routing ----
    const int rbid = bid - NA_BLOCKS - RW_BLOCKS;
    for (int i = tid; i < E_EXP * D_DIM; i += blockDim.x) sgw[i] = gw[i];
    __syncthreads();
    const int warp = tid >> 5, lane = tid & 31;
    const int t = rbid * 8 + warp;
    const float* xt = x + (long long)t * D_DIM;
    float acc[E_EXP];
#pragma unroll
    for (int e = 0; e < E_EXP; e++) acc[e] = 0.f;
    for (int k = lane; k < D_DIM; k += 32) {
        float xv = xt[k];
#pragma unroll
        for (int e = 0; e < E_EXP; e++) acc[e] += xv * sgw[e * D_DIM + k];
    }
#pragma unroll
    for (int e = 0; e < E_EXP; e++)
#pragma unroll
        for (int off = 16; off; off >>= 1)
            acc[e] += __shfl_xor_sync(0xffffffffu, acc[e], off);
    if (lane == 0) {
        float mx = acc[0];
#pragma unroll
        for (int e = 1; e < E_EXP; e++) mx = fmaxf(mx, acc[e]);
        float p[E_EXP], Z = 0.f;
#pragma unroll
        for (int e = 0; e < E_EXP; e++) { p[e] = expf(acc[e] - mx); Z += p[e]; }
#pragma unroll
        for (int e = 0; e < E_EXP; e++) p[e] /= Z;
        int i1 = 0;
#pragma unroll
        for (int e = 1; e < E_EXP; e++) if (p[e] > p[i1]) i1 = e;
        int i2 = (i1 == 0) ? 1 : 0;
#pragma unroll
        for (int e = 0; e < E_EXP; e++) if (e != i1 && e != i2 && p[e] > p[i2]) i2 = e;
        float denom = p[i1] + p[i2] + 1e-8f;
        int pos1 = atomicAdd(&cnt[i1], 1);
        tok[i1 * T_TOKENS + pos1] = t;
        int pos2 = atomicAdd(&cnt[i2], 1);
        tok[i2 * T_TOKENS + pos2] = t;
        tk2[t] = make_int4(i1, pos1, i2, pos2);
        w2[t]  = make_float2(p[i1] / denom, p[i2] / denom);
    }
}

// ---------------- host launch ----------------
extern "C" void kernel_launch(void* const* d_in, const int* in_sizes, int n_in,
                              void* d_out, int out_size) {
    const float* x   = (const float*)d_in[0];
    const float* gw  = (const float*)d_in[1];
    const float* sgu = (const float*)d_in[2];
    const float* sdn = (const float*)d_in[3];
    const float* egu = (const float*)d_in[4];
    const float* edn = (const float*)d_in[5];
    float* out = (float*)d_out;

    cudaFuncSetAttribute(gemm1_kernel, cudaFuncAttributeMaxDynamicSharedMemorySize, SMEM_DYN);
    cudaFuncSetAttribute(gemm2_kernel, cudaFuncAttributeMaxDynamicSharedMemorySize, SMEM_DYN);

    void *pCnt, *pTok, *pTk2, *pW2, *pX16, *pWgu, *pWdn;
    cudaGetSymbolAddress(&pCnt, g_cnt);
    cudaGetSymbolAddress(&pTok, g_tok);
    cudaGetSymbolAddress(&pTk2, g_tk2);
    cudaGetSymbolAddress(&pW2,  g_w2);
    cudaGetSymbolAddress(&pX16, g_x16);
    cudaGetSymbolAddress(&pWgu, g_wgu);
    cudaGetSymbolAddress(&pWdn, g_wdn);

    // #1: fused setup (cvt x, repack weights, router) — g_cnt==0 invariant on entry
    setup_kernel<<<NA_BLOCKS + RW_BLOCKS + RT_BLOCKS, 256>>>(
        x, (fp16*)pX16, gw, sgu, egu, sdn, edn,
        (fp16*)pWgu, (fp16*)pWdn,
        (int*)pCnt, (int*)pTok, (int4*)pTk2, (float2*)pW2);

    // #2: GEMM1 + fused swiglu (shared + routed) — fp16-acc experiment
    gemm1_kernel<<<dim3(GUP / BN, T_TOKENS / BM, NSLOT), NTHR, SMEM_DYN>>>();

    // #3: GEMM2: slot 0 writes out, slots 1..8 write ybuf (fp16)
    gemm2_kernel<<<dim3(D_DIM / BN, T_TOKENS / BM, NSLOT), NTHR, SMEM_DYN>>>(out);

    // #4: combine routed contributions (atomic-free) + restore cnt invariant
    combine_kernel<<<T_TOKENS, 256>>>(out);
}

// round 14
// speedup vs baseline: 1.2354x; 1.2354x over previous
#include <cuda_runtime.h>
#include <cuda_fp16.h>
#include <math.h>
#include <stdint.h>

typedef __half fp16;

#define T_TOKENS 8192
#define D_DIM    1024
#define E_EXP    8
#define I_DIM    938
#define GU_DIM   1876
#define GUP      1920      // 2I padded (15*128)
#define IP       960       // I padded (15*64)
#define NSLOT    9         // slot0 = shared, 1..8 = routed

#define BM 128
#define BN 128
#define BK 64
#define SROW 144                        // 64 fp16 = 128B data + 16B pad
#define OFF_A 0
#define OFF_B (BM*SROW)                 // 18432
#define STAGEB ((BM+BN)*SROW)           // 36864
#define NSTAGE 3
#define SMEM_DYN (1024 + NSTAGE*STAGEB) // 111616

// ---------------- static scratch ----------------
__device__ int    g_cnt[E_EXP];
__device__ int    g_tok[E_EXP * T_TOKENS];
__device__ int4   g_tk2[T_TOKENS];
__device__ float2 g_w2 [T_TOKENS];
__device__ fp16   g_x16[T_TOKENS * D_DIM];
__device__ fp16   g_wgu[NSLOT * GUP * D_DIM];     // interleaved (gate_i, up_i) rows
__device__ fp16   g_wdn[NSLOT * D_DIM * IP];
__device__ fp16   g_act[(size_t)NSLOT * T_TOKENS * IP];
__device__ fp16   g_ybuf[(size_t)E_EXP * T_TOKENS * D_DIM];

// ---------------- helpers ----------------
__device__ __forceinline__ uint32_t smem_u32(const void* p) {
    uint32_t a;
    asm("{ .reg .u64 t; cvta.to.shared.u64 t, %1; cvt.u32.u64 %0, t; }" : "=r"(a) : "l"(p));
    return a;
}
__device__ __forceinline__ void cp16(uint32_t s, const void* g) {
    asm volatile("cp.async.cg.shared.global [%0], [%1], 16;" :: "r"(s), "l"(g));
}
__device__ __forceinline__ void ldsm4(uint32_t* r, uint32_t a) {
    asm volatile("ldmatrix.sync.aligned.m8n8.x4.shared.b16 {%0,%1,%2,%3}, [%4];"
        : "=r"(r[0]), "=r"(r[1]), "=r"(r[2]), "=r"(r[3]) : "r"(a));
}
__device__ __forceinline__ void mma16816(float* d, const uint32_t* a, const uint32_t* b) {
    asm volatile(
        "mma.sync.aligned.m16n8k16.row.col.f32.f16.f16.f32 "
        "{%0,%1,%2,%3}, {%4,%5,%6,%7}, {%8,%9}, {%0,%1,%2,%3};"
        : "+f"(d[0]), "+f"(d[1]), "+f"(d[2]), "+f"(d[3])
        : "r"(a[0]), "r"(a[1]), "r"(a[2]), "r"(a[3]), "r"(b[0]), "r"(b[1]));
}

// ---------- mainloop: 128x128 CTA tile, 64x32 warp tile (2x4), 3-stage, 1 sync/chunk --
__device__ __forceinline__ void gemm_mainloop(
    uint32_t s0,
    const fp16* sa,                       // per-thread A row ptr (row = tid>>1)
    const fp16* sb,                       // per-thread B row ptr (row = tid>>1)
    int NC, int tid, float acc[4][4][4])
{
    const int lane = tid & 31, wid = tid >> 5;
    const uint32_t rowoff = (uint32_t)(tid >> 1) * SROW + (uint32_t)(tid & 1) * 64;
    const int kel = (tid & 1) * 32;

#define LOAD_STAGE(st, c) do {                                              \
        uint32_t base_ = s0 + (st) * STAGEB;                                \
        int k0_ = (c) * BK + kel;                                           \
        _Pragma("unroll")                                                   \
        for (int j = 0; j < 4; j++) {                                       \
            cp16(base_ + OFF_A + rowoff + j*16, sa + k0_ + j*8);            \
            cp16(base_ + OFF_B + rowoff + j*16, sb + k0_ + j*8);            \
        }                                                                   \
        asm volatile("cp.async.commit_group;" ::: "memory");                \
    } while (0)

    LOAD_STAGE(0, 0);
    LOAD_STAGE(1, 1);    // NC >= 2 always (min NC = 15)

    const int mwb = (wid >> 2) * 64;
    const int nwb = (wid & 3) * 32;
    const int arow   = mwb + (lane & 15);
    const int acolB0 = (lane >> 4) * 16;
    const int bnrow  = nwb + ((lane >> 4) * 8) + (lane & 7);
    const int bkB0   = ((lane >> 3) & 1) * 16;

    int st = 0;
    for (int c = 0; c < NC; c++) {
        if (c + 1 < NC) asm volatile("cp.async.wait_group 1;" ::: "memory");
        else            asm volatile("cp.async.wait_group 0;" ::: "memory");
        __syncthreads();
        if (c + 2 < NC) {
            int ls = st + 2; if (ls >= NSTAGE) ls -= NSTAGE;
            LOAD_STAGE(ls, c + 2);
        }
        const uint32_t tb = s0 + st * STAGEB;
#pragma unroll
        for (int ks = 0; ks < 4; ks++) {
            const uint32_t acolB = ks * 32 + acolB0;
            const uint32_t bcolB = ks * 32 + bkB0;
            uint32_t ah[4][4];
#pragma unroll
            for (int mi = 0; mi < 4; mi++)
                ldsm4(ah[mi], tb + OFF_A + (uint32_t)(arow + mi * 16) * SROW + acolB);
#pragma unroll
            for (int nb = 0; nb < 2; nb++) {
                uint32_t bh[4];
                ldsm4(bh, tb + OFF_B + (uint32_t)(bnrow + nb * 16) * SROW + bcolB);
#pragma unroll
                for (int mi = 0; mi < 4; mi++) {
                    mma16816(acc[mi][nb * 2 + 0], ah[mi], bh + 0);
                    mma16816(acc[mi][nb * 2 + 1], ah[mi], bh + 2);
                }
            }
        }
        st++; if (st == NSTAGE) st = 0;
    }
#undef LOAD_STAGE
}

// ---------------- GEMM1: H = X @ Wgu^T, fused swiglu -> act fp16 ----------------
__global__ void __launch_bounds__(256, 2) gemm1_kernel() {
    extern __shared__ char smem[];
    int* rowids = (int*)smem;
    const uint32_t s0 = smem_u32(smem) + 1024;
    const int tid = threadIdx.x;
    const int s = blockIdx.z, m0 = blockIdx.y * BM, n0 = blockIdx.x * BN;
    const int M = (s == 0) ? T_TOKENS : g_cnt[s - 1];
    if (m0 >= M) return;

    if (tid < BM) {
        int am = m0 + tid;
        int r;
        if (s == 0) r = (am < M ? am : M - 1);
        else        r = g_tok[(s - 1) * T_TOKENS + (am < M ? am : M - 1)];
        rowids[tid] = r;
    }
    __syncthreads();

    const fp16* sa = g_x16 + (long long)rowids[tid >> 1] * D_DIM;
    const fp16* sb = g_wgu + ((long long)s * GUP + n0 + (tid >> 1)) * D_DIM;

    float acc[4][4][4];
#pragma unroll
    for (int i = 0; i < 4; i++)
#pragma unroll
        for (int j = 0; j < 4; j++)
#pragma unroll
            for (int k = 0; k < 4; k++) acc[i][j][k] = 0.f;

    gemm_mainloop(s0, sa, sb, D_DIM / BK, tid, acc);

    const int lane = tid & 31, wid = tid >> 5;
    const int mwb = (wid >> 2) * 64, nwb = (wid & 3) * 32;
    fp16* oa = g_act + (size_t)s * T_TOKENS * IP;
#pragma unroll
    for (int mi = 0; mi < 4; mi++) {
        const int r0 = m0 + mwb + mi * 16 + (lane >> 2);
#pragma unroll
        for (int j = 0; j < 4; j++) {
            const int nbase = n0 + nwb + j * 8 + (lane & 3) * 2;
            const int acol = nbase >> 1;
            const float* a = acc[mi][j];
            if (r0 < M) {
                float g = a[0], u = a[1];
                float v = (g / (1.f + __expf(-g))) * u;
                oa[(size_t)r0 * IP + acol] = __float2half(v);
            }
            if (r0 + 8 < M) {
                float g = a[2], u = a[3];
                float v = (g / (1.f + __expf(-g))) * u;
                oa[(size_t)(r0 + 8) * IP + acol] = __float2half(v);
            }
        }
    }
}

// ---------------- GEMM2: C = act @ down^T (slot0 -> out fp32, 1..8 -> ybuf fp16) ------
__global__ void __launch_bounds__(256, 2) gemm2_kernel(float* __restrict__ out) {
    extern __shared__ char smem[];
    const uint32_t s0 = smem_u32(smem) + 1024;
    const int tid = threadIdx.x;
    const int s = blockIdx.z, m0 = blockIdx.y * BM, n0 = blockIdx.x * BN;
    const int M = (s == 0) ? T_TOKENS : g_cnt[s - 1];
    if (m0 >= M) return;

    const int amr = m0 + (tid >> 1) < T_TOKENS ? m0 + (tid >> 1) : T_TOKENS - 1;
    const fp16* sa = g_act + (size_t)s * T_TOKENS * IP + (size_t)amr * IP;
    const fp16* sb = g_wdn + ((long long)s * D_DIM + n0 + (tid >> 1)) * IP;

    float acc[4][4][4];
#pragma unroll
    for (int i = 0; i < 4; i++)
#pragma unroll
        for (int j = 0; j < 4; j++)
#pragma unroll
            for (int k = 0; k < 4; k++) acc[i][j][k] = 0.f;

    gemm_mainloop(s0, sa, sb, IP / BK, tid, acc);

    const int lane = tid & 31, wid = tid >> 5;
    const int mwb = (wid >> 2) * 64, nwb = (wid & 3) * 32;
    if (s == 0) {
#pragma unroll
        for (int mi = 0; mi < 4; mi++) {
            const int r0 = m0 + mwb + mi * 16 + (lane >> 2);
#pragma unroll
            for (int j = 0; j < 4; j++) {
                const int n = n0 + nwb + j * 8 + (lane & 3) * 2;
                const float* a = acc[mi][j];
                if (r0 < M)     *(float2*)(out + (size_t)r0 * D_DIM + n)       = make_float2(a[0], a[1]);
                if (r0 + 8 < M) *(float2*)(out + (size_t)(r0 + 8) * D_DIM + n) = make_float2(a[2], a[3]);
            }
        }
    } else {
        fp16* C = g_ybuf + (size_t)(s - 1) * T_TOKENS * D_DIM;
#pragma unroll
        for (int mi = 0; mi < 4; mi++) {
            const int r0 = m0 + mwb + mi * 16 + (lane >> 2);
#pragma unroll
            for (int j = 0; j < 4; j++) {
                const int n = n0 + nwb + j * 8 + (lane & 3) * 2;
                const float* a = acc[mi][j];
                if (r0 < M) {
                    __align__(4) fp16 h[2] = {__float2half(a[0]), __float2half(a[1])};
                    *(uint32_t*)(C + (size_t)r0 * D_DIM + n) = *(const uint32_t*)h;
                }
                if (r0 + 8 < M) {
                    __align__(4) fp16 h[2] = {__float2half(a[2]), __float2half(a[3])};
                    *(uint32_t*)(C + (size_t)(r0 + 8) * D_DIM + n) = *(const uint32_t*)h;
                }
            }
        }
    }
}

// ---------------- combine: out[t] += w1*y[e1][p1] + w2*y[e2][p2] (fp16 ybuf) ----------
__global__ void combine_kernel(float* __restrict__ out) {
    const int t = blockIdx.x;
    const int c = threadIdx.x;                // 256 threads x 4 floats = 1024
    const int4 e = g_tk2[t];
    const float2 w = g_w2[t];
    const uint2* y1 = (const uint2*)(g_ybuf + ((size_t)e.x * T_TOKENS + e.y) * D_DIM);
    const uint2* y2 = (const uint2*)(g_ybuf + ((size_t)e.z * T_TOKENS + e.w) * D_DIM);
    float4* o = (float4*)(out + (size_t)t * D_DIM);
    uint2 p1 = y1[c], p2 = y2[c];
    float2 a1 = __half22float2(*(const __half2*)&p1.x);
    float2 b1 = __half22float2(*(const __half2*)&p1.y);
    float2 a2 = __half22float2(*(const __half2*)&p2.x);
    float2 b2 = __half22float2(*(const __half2*)&p2.y);
    float4 a = o[c];
    a.x += w.x * a1.x + w.y * a2.x;
    a.y += w.x * a1.y + w.y * a2.y;
    a.z += w.x * b1.x + w.y * b2.x;
    a.w += w.x * b1.y + w.y * b2.y;
    o[c] = a;
}

// ---------------- fused setup: cvt_x + zero counters + repack wgu/wdn ----------------
// grid.x = NA + (GUP + D_DIM)*NSLOT, block 256
#define NA_BLOCKS (T_TOKENS * D_DIM / 1024)   // 8192
__global__ void setup_kernel(const float* __restrict__ x, fp16* __restrict__ xo,
                             int* __restrict__ cnt,
                             const float* __restrict__ sgu, const float* __restrict__ egu,
                             const float* __restrict__ sdn, const float* __restrict__ edn,
                             fp16* __restrict__ wgu, fp16* __restrict__ wdn) {
    const int bid = blockIdx.x;
    if (bid < NA_BLOCKS) {
        // ---- cvt x -> fp16, zero counters ----
        if (bid == 0 && threadIdx.x < E_EXP) cnt[threadIdx.x] = 0;
        const int i4 = (bid * 256 + threadIdx.x) * 4;
        float4 v = *(const float4*)(x + i4);
        __align__(8) fp16 h[4];
        h[0] = __float2half(v.x); h[1] = __float2half(v.y);
        h[2] = __float2half(v.z); h[3] = __float2half(v.w);
        *(uint2*)(xo + i4) = *(const uint2*)h;
        return;
    }
    const int bid2 = bid - NA_BLOCKS;
    const int s = bid2 / (GUP + D_DIM);
    const int rr = bid2 - s * (GUP + D_DIM);
    if (rr < GUP) {
        // ---- repack gate_up (interleave gate_i/up_i rows, pad to GUP) ----
        const int r = rr;
        const int k4 = threadIdx.x * 4;
        const size_t dst = ((size_t)s * GUP + r) * D_DIM + k4;
        float4 v = make_float4(0.f, 0.f, 0.f, 0.f);
        if (r < GU_DIM) {
            const int sr = (r & 1) ? (r >> 1) + I_DIM : (r >> 1);
            const float* src = (s == 0) ? (sgu + (size_t)sr * D_DIM)
                                        : (egu + ((size_t)(s - 1) * GU_DIM + sr) * D_DIM);
            v = *(const float4*)(src + k4);
        }
        __align__(8) fp16 h[4];
        h[0] = __float2half(v.x); h[1] = __float2half(v.y);
        h[2] = __float2half(v.z); h[3] = __float2half(v.w);
        *(uint2*)(wgu + dst) = *(const uint2*)h;
    } else {
        // ---- repack down (pad K to IP) ----
        if (threadIdx.x >= 240) return;
        const int n = rr - GUP;
        const int k4 = threadIdx.x * 4;
        const size_t dst = ((size_t)s * D_DIM + n) * IP + k4;
        const float* src = (s == 0) ? (sdn + (size_t)n * I_DIM)
                                    : (edn + ((size_t)(s - 1) * D_DIM + n) * I_DIM);
        __align__(8) fp16 h[4];
#pragma unroll
        for (int q = 0; q < 4; q++) {
            const int i = k4 + q;
            float v = (i < I_DIM) ? __ldg(src + i) : 0.f;
            h[q] = __float2half(v);
        }
        *(uint2*)(wdn + dst) = *(const uint2*)h;
    }
}

// ---------------- router (fp32, bit-identical routing) ----------------
__global__ void router_kernel(const float* __restrict__ x, const float* __restrict__ gw,
                              int* __restrict__ cnt, int* __restrict__ tok,
                              int4* __restrict__ tk2, float2* __restrict__ w2) {
    __shared__ float sgw[E_EXP * D_DIM];
    const int tid = threadIdx.x;
    for (int i = tid; i < E_EXP * D_DIM; i += blockDim.x) sgw[i] = gw[i];
    __syncthreads();
    const int warp = tid >> 5, lane = tid & 31;
    const int t = blockIdx.x * 8 + warp;
    const float* xt = x + (long long)t * D_DIM;
    float acc[E_EXP];
#pragma unroll
    for (int e = 0; e < E_EXP; e++) acc[e] = 0.f;
    for (int k = lane; k < D_DIM; k += 32) {
        float xv = xt[k];
#pragma unroll
        for (int e = 0; e < E_EXP; e++) acc[e] += xv * sgw[e * D_DIM + k];
    }
#pragma unroll
    for (int e = 0; e < E_EXP; e++)
#pragma unroll
        for (int off = 16; off; off >>= 1)
            acc[e] += __shfl_xor_sync(0xffffffffu, acc[e], off);
    if (lane == 0) {
        float mx = acc[0];
#pragma unroll
        for (int e = 1; e < E_EXP; e++) mx = fmaxf(mx, acc[e]);
        float p[E_EXP], Z = 0.f;
#pragma unroll
        for (int e = 0; e < E_EXP; e++) { p[e] = expf(acc[e] - mx); Z += p[e]; }
#pragma unroll
        for (int e = 0; e < E_EXP; e++) p[e] /= Z;
        int i1 = 0;
#pragma unroll
        for (int e = 1; e < E_EXP; e++) if (p[e] > p[i1]) i1 = e;
        int i2 = (i1 == 0) ? 1 : 0;
#pragma unroll
        for (int e = 0; e < E_EXP; e++) if (e != i1 && e != i2 && p[e] > p[i2]) i2 = e;
        float denom = p[i1] + p[i2] + 1e-8f;
        int pos1 = atomicAdd(&cnt[i1], 1);
        tok[i1 * T_TOKENS + pos1] = t;
        int pos2 = atomicAdd(&cnt[i2], 1);
        tok[i2 * T_TOKENS + pos2] = t;
        tk2[t] = make_int4(i1, pos1, i2, pos2);
        w2[t]  = make_float2(p[i1] / denom, p[i2] / denom);
    }
}

// ---------------- host launch ----------------
extern "C" void kernel_launch(void* const* d_in, const int* in_sizes, int n_in,
                              void* d_out, int out_size) {
    const float* x   = (const float*)d_in[0];
    const float* gw  = (const float*)d_in[1];
    const float* sgu = (const float*)d_in[2];
    const float* sdn = (const float*)d_in[3];
    const float* egu = (const float*)d_in[4];
    const float* edn = (const float*)d_in[5];
    float* out = (float*)d_out;

    cudaFuncSetAttribute(gemm1_kernel, cudaFuncAttributeMaxDynamicSharedMemorySize, SMEM_DYN);
    cudaFuncSetAttribute(gemm2_kernel, cudaFuncAttributeMaxDynamicSharedMemorySize, SMEM_DYN);

    void *pCnt, *pTok, *pTk2, *pW2, *pX16, *pWgu, *pWdn;
    cudaGetSymbolAddress(&pCnt, g_cnt);
    cudaGetSymbolAddress(&pTok, g_tok);
    cudaGetSymbolAddress(&pTk2, g_tk2);
    cudaGetSymbolAddress(&pW2,  g_w2);
    cudaGetSymbolAddress(&pX16, g_x16);
    cudaGetSymbolAddress(&pWgu, g_wgu);
    cudaGetSymbolAddress(&pWdn, g_wdn);

    // #1: fused setup (cvt x, zero counters, repack both weight sets)
    setup_kernel<<<NA_BLOCKS + (GUP + D_DIM) * NSLOT, 256>>>(
        x, (fp16*)pX16, (int*)pCnt, sgu, egu, sdn, edn, (fp16*)pWgu, (fp16*)pWdn);

    // #2: router
    router_kernel<<<T_TOKENS / 8, 256>>>(x, gw, (int*)pCnt, (int*)pTok,
                                         (int4*)pTk2, (float2*)pW2);

    // #3: GEMM1 + fused swiglu
    gemm1_kernel<<<dim3(GUP / BN, T_TOKENS / BM, NSLOT), 256, SMEM_DYN>>>();

    // #4: GEMM2: slot 0 writes out, slots 1..8 write ybuf (fp16)
    gemm2_kernel<<<dim3(D_DIM / BN, T_TOKENS / BM, NSLOT), 256, SMEM_DYN>>>(out);

    // #5: combine routed contributions (atomic-free)
    combine_kernel<<<T_TOKENS, 256>>>(out);
}

// round 15
// speedup vs baseline: 1.2820x; 1.0377x over previous
#include <cuda_runtime.h>
#include <cuda_fp16.h>
#include <math.h>
#include <stdint.h>

typedef __half fp16;

#define T_TOKENS 8192
#define D_DIM    1024
#define E_EXP    8
#define I_DIM    938
#define GU_DIM   1876
#define GUP      1920      // 2I padded (15*128)
#define IP       960       // I padded (15*64)
#define NSLOT    9         // slot0 = shared, 1..8 = routed

#define BM 128
#define BN 128
#define BK 64
#define MB_CNT   (T_TOKENS / BM)        // 64 m-blocks
#define G1_NB    (GUP / BN)             // 15
#define G2_NB    (D_DIM / BN)           // 8
#define G1_BLOCKS (NSLOT * MB_CNT * G1_NB)   // 8640
#define G2_BLOCKS (NSLOT * MB_CNT * G2_NB)   // 4608
#define SROW 144                        // 64 fp16 = 128B data + 16B pad
#define OFF_A 0
#define OFF_B (BM*SROW)                 // 18432
#define STAGEB ((BM+BN)*SROW)           // 36864
#define NSTAGE 3
#define SMEM_DYN (1024 + NSTAGE*STAGEB) // 111616

// ---------------- static scratch ----------------
__device__ int    g_cnt[E_EXP];
__device__ int    g_done[NSLOT * MB_CNT];   // zero at load; combine restores zero
__device__ int    g_tok[E_EXP * T_TOKENS];
__device__ int4   g_tk2[T_TOKENS];
__device__ float2 g_w2 [T_TOKENS];
__device__ fp16   g_x16[T_TOKENS * D_DIM];
__device__ fp16   g_wgu[NSLOT * GUP * D_DIM];     // interleaved (gate_i, up_i) rows
__device__ fp16   g_wdn[NSLOT * D_DIM * IP];
__device__ fp16   g_act[(size_t)NSLOT * T_TOKENS * IP];
__device__ fp16   g_ybuf[(size_t)E_EXP * T_TOKENS * D_DIM];

// ---------------- helpers ----------------
__device__ __forceinline__ uint32_t smem_u32(const void* p) {
    uint32_t a;
    asm("{ .reg .u64 t; cvta.to.shared.u64 t, %1; cvt.u32.u64 %0, t; }" : "=r"(a) : "l"(p));
    return a;
}
__device__ __forceinline__ void cp16(uint32_t s, const void* g) {
    asm volatile("cp.async.cg.shared.global [%0], [%1], 16;" :: "r"(s), "l"(g));
}
__device__ __forceinline__ void ldsm4(uint32_t* r, uint32_t a) {
    asm volatile("ldmatrix.sync.aligned.m8n8.x4.shared.b16 {%0,%1,%2,%3}, [%4];"
        : "=r"(r[0]), "=r"(r[1]), "=r"(r[2]), "=r"(r[3]) : "r"(a));
}
__device__ __forceinline__ void mma16816(float* d, const uint32_t* a, const uint32_t* b) {
    asm volatile(
        "mma.sync.aligned.m16n8k16.row.col.f32.f16.f16.f32 "
        "{%0,%1,%2,%3}, {%4,%5,%6,%7}, {%8,%9}, {%0,%1,%2,%3};"
        : "+f"(d[0]), "+f"(d[1]), "+f"(d[2]), "+f"(d[3])
        : "r"(a[0]), "r"(a[1]), "r"(a[2]), "r"(a[3]), "r"(b[0]), "r"(b[1]));
}

// ---------- mainloop: 128x128 CTA tile, 64x32 warp tile (2x4), 3-stage, 1 sync/chunk --
__device__ __forceinline__ void gemm_mainloop(
    uint32_t s0,
    const fp16* sa,                       // per-thread A row ptr (row = tid>>1)
    const fp16* sb,                       // per-thread B row ptr (row = tid>>1)
    int NC, int tid, float acc[4][4][4])
{
    const int lane = tid & 31, wid = tid >> 5;
    const uint32_t rowoff = (uint32_t)(tid >> 1) * SROW + (uint32_t)(tid & 1) * 64;
    const int kel = (tid & 1) * 32;

#define LOAD_STAGE(st, c) do {                                              \
        uint32_t base_ = s0 + (st) * STAGEB;                                \
        int k0_ = (c) * BK + kel;                                           \
        _Pragma("unroll")                                                   \
        for (int j = 0; j < 4; j++) {                                       \
            cp16(base_ + OFF_A + rowoff + j*16, sa + k0_ + j*8);            \
            cp16(base_ + OFF_B + rowoff + j*16, sb + k0_ + j*8);            \
        }                                                                   \
        asm volatile("cp.async.commit_group;" ::: "memory");                \
    } while (0)

    LOAD_STAGE(0, 0);
    LOAD_STAGE(1, 1);    // NC >= 2 always (min NC = 15)

    const int mwb = (wid >> 2) * 64;
    const int nwb = (wid & 3) * 32;
    const int arow   = mwb + (lane & 15);
    const int acolB0 = (lane >> 4) * 16;
    const int bnrow  = nwb + ((lane >> 4) * 8) + (lane & 7);
    const int bkB0   = ((lane >> 3) & 1) * 16;

    int st = 0;
    for (int c = 0; c < NC; c++) {
        if (c + 1 < NC) asm volatile("cp.async.wait_group 1;" ::: "memory");
        else            asm volatile("cp.async.wait_group 0;" ::: "memory");
        __syncthreads();
        if (c + 2 < NC) {
            int ls = st + 2; if (ls >= NSTAGE) ls -= NSTAGE;
            LOAD_STAGE(ls, c + 2);
        }
        const uint32_t tb = s0 + st * STAGEB;
#pragma unroll
        for (int ks = 0; ks < 4; ks++) {
            const uint32_t acolB = ks * 32 + acolB0;
            const uint32_t bcolB = ks * 32 + bkB0;
            uint32_t ah[4][4];
#pragma unroll
            for (int mi = 0; mi < 4; mi++)
                ldsm4(ah[mi], tb + OFF_A + (uint32_t)(arow + mi * 16) * SROW + acolB);
#pragma unroll
            for (int nb = 0; nb < 2; nb++) {
                uint32_t bh[4];
                ldsm4(bh, tb + OFF_B + (uint32_t)(bnrow + nb * 16) * SROW + bcolB);
#pragma unroll
                for (int mi = 0; mi < 4; mi++) {
                    mma16816(acc[mi][nb * 2 + 0], ah[mi], bh + 0);
                    mma16816(acc[mi][nb * 2 + 1], ah[mi], bh + 2);
                }
            }
        }
        st++; if (st == NSTAGE) st = 0;
    }
#undef LOAD_STAGE
}

// ---- fused GEMM kernel: blocks [0,G1) produce act (gemm1), [G1,G1+G2) consume (gemm2)
// Per-(s, mb) row-band flags let gemm2 tiles start as soon as their 15 producers finish.
__global__ void __launch_bounds__(256, 2) gemm_fused_kernel(float* __restrict__ out) {
    extern __shared__ char smem[];
    const uint32_t s0 = smem_u32(smem) + 1024;
    const int tid = threadIdx.x;
    const int lane = tid & 31, wid = tid >> 5;
    const int mwb = (wid >> 2) * 64, nwb = (wid & 3) * 32;

    if (blockIdx.x < G1_BLOCKS) {
        // =================== GEMM1: H = X @ Wgu^T, fused swiglu -> act ===================
        const int s  = blockIdx.x / (MB_CNT * G1_NB);
        const int r_ = blockIdx.x - s * (MB_CNT * G1_NB);
        const int mb = r_ / G1_NB;
        const int nb_ = r_ - mb * G1_NB;
        const int m0 = mb * BM, n0 = nb_ * BN;
        const int M = (s == 0) ? T_TOKENS : g_cnt[s - 1];
        if (m0 >= M) return;                 // consumer for this (s,mb) is dead too

        int* rowids = (int*)smem;
        if (tid < BM) {
            int am = m0 + tid;
            int r;
            if (s == 0) r = (am < M ? am : M - 1);
            else        r = g_tok[(s - 1) * T_TOKENS + (am < M ? am : M - 1)];
            rowids[tid] = r;
        }
        __syncthreads();

        const fp16* sa = g_x16 + (long long)rowids[tid >> 1] * D_DIM;
        const fp16* sb = g_wgu + ((long long)s * GUP + n0 + (tid >> 1)) * D_DIM;

        float acc[4][4][4];
#pragma unroll
        for (int i = 0; i < 4; i++)
#pragma unroll
            for (int j = 0; j < 4; j++)
#pragma unroll
                for (int k = 0; k < 4; k++) acc[i][j][k] = 0.f;

        gemm_mainloop(s0, sa, sb, D_DIM / BK, tid, acc);

        fp16* oa = g_act + (size_t)s * T_TOKENS * IP;
#pragma unroll
        for (int mi = 0; mi < 4; mi++) {
            const int r0 = m0 + mwb + mi * 16 + (lane >> 2);
#pragma unroll
            for (int j = 0; j < 4; j++) {
                const int nbase = n0 + nwb + j * 8 + (lane & 3) * 2;
                const int acol = nbase >> 1;
                const float* a = acc[mi][j];
                if (r0 < M) {
                    float g = a[0], u = a[1];
                    float v = (g / (1.f + __expf(-g))) * u;
                    oa[(size_t)r0 * IP + acol] = __float2half(v);
                }
                if (r0 + 8 < M) {
                    float g = a[2], u = a[3];
                    float v = (g / (1.f + __expf(-g))) * u;
                    oa[(size_t)(r0 + 8) * IP + acol] = __float2half(v);
                }
            }
        }
        // release: make act writes visible, then signal this (s, mb) row-band
        __threadfence();
        __syncthreads();
        if (tid == 0) atomicAdd(&g_done[s * MB_CNT + mb], 1);
        return;
    }

    // =================== GEMM2: C = act @ down^T ===================
    const int b2 = blockIdx.x - G1_BLOCKS;
    const int s  = b2 / (MB_CNT * G2_NB);
    const int r_ = b2 - s * (MB_CNT * G2_NB);
    const int mb = r_ / G2_NB;
    const int nb_ = r_ - mb * G2_NB;
    const int m0 = mb * BM, n0 = nb_ * BN;
    const int M = (s == 0) ? T_TOKENS : g_cnt[s - 1];
    if (m0 >= M) return;

    // acquire: wait until all 15 producers of this (s, mb) row-band are done
    if (tid == 0) {
        while (atomicAdd(&g_done[s * MB_CNT + mb], 0) < G1_NB)
            __nanosleep(128);
    }
    __syncthreads();
    __threadfence();

    const int amr = m0 + (tid >> 1) < T_TOKENS ? m0 + (tid >> 1) : T_TOKENS - 1;
    const fp16* sa = g_act + (size_t)s * T_TOKENS * IP + (size_t)amr * IP;
    const fp16* sb = g_wdn + ((long long)s * D_DIM + n0 + (tid >> 1)) * IP;

    float acc[4][4][4];
#pragma unroll
    for (int i = 0; i < 4; i++)
#pragma unroll
        for (int j = 0; j < 4; j++)
#pragma unroll
            for (int k = 0; k < 4; k++) acc[i][j][k] = 0.f;

    gemm_mainloop(s0, sa, sb, IP / BK, tid, acc);

    if (s == 0) {
#pragma unroll
        for (int mi = 0; mi < 4; mi++) {
            const int r0 = m0 + mwb + mi * 16 + (lane >> 2);
#pragma unroll
            for (int j = 0; j < 4; j++) {
                const int n = n0 + nwb + j * 8 + (lane & 3) * 2;
                const float* a = acc[mi][j];
                if (r0 < M)     *(float2*)(out + (size_t)r0 * D_DIM + n)       = make_float2(a[0], a[1]);
                if (r0 + 8 < M) *(float2*)(out + (size_t)(r0 + 8) * D_DIM + n) = make_float2(a[2], a[3]);
            }
        }
    } else {
        fp16* C = g_ybuf + (size_t)(s - 1) * T_TOKENS * D_DIM;
#pragma unroll
        for (int mi = 0; mi < 4; mi++) {
            const int r0 = m0 + mwb + mi * 16 + (lane >> 2);
#pragma unroll
            for (int j = 0; j < 4; j++) {
                const int n = n0 + nwb + j * 8 + (lane & 3) * 2;
                const float* a = acc[mi][j];
                if (r0 < M) {
                    __align__(4) fp16 h[2] = {__float2half(a[0]), __float2half(a[1])};
                    *(uint32_t*)(C + (size_t)r0 * D_DIM + n) = *(const uint32_t*)h;
                }
                if (r0 + 8 < M) {
                    __align__(4) fp16 h[2] = {__float2half(a[2]), __float2half(a[3])};
                    *(uint32_t*)(C + (size_t)(r0 + 8) * D_DIM + n) = *(const uint32_t*)h;
                }
            }
        }
    }
}

// ---- combine: out[t] += w1*y[e1][p1] + w2*y[e2][p2]; restore g_done==0 invariant ----
__global__ void combine_kernel(float* __restrict__ out) {
    const int t = blockIdx.x;
    const int c = threadIdx.x;                // 256 threads x 4 floats = 1024
    if (t < NSLOT * MB_CNT && c == 0) g_done[t] = 0;   // reset flags for next call
    const int4 e = g_tk2[t];
    const float2 w = g_w2[t];
    const uint2* y1 = (const uint2*)(g_ybuf + ((size_t)e.x * T_TOKENS + e.y) * D_DIM);
    const uint2* y2 = (const uint2*)(g_ybuf + ((size_t)e.z * T_TOKENS + e.w) * D_DIM);
    float4* o = (float4*)(out + (size_t)t * D_DIM);
    uint2 p1 = y1[c], p2 = y2[c];
    float2 a1 = __half22float2(*(const __half2*)&p1.x);
    float2 b1 = __half22float2(*(const __half2*)&p1.y);
    float2 a2 = __half22float2(*(const __half2*)&p2.x);
    float2 b2 = __half22float2(*(const __half2*)&p2.y);
    float4 a = o[c];
    a.x += w.x * a1.x + w.y * a2.x;
    a.y += w.x * a1.y + w.y * a2.y;
    a.z += w.x * b1.x + w.y * b2.x;
    a.w += w.x * b1.y + w.y * b2.y;
    o[c] = a;
}

// ---------------- fused setup: cvt_x + zero counters + repack wgu/wdn ----------------
#define NA_BLOCKS (T_TOKENS * D_DIM / 1024)   // 8192
__global__ void setup_kernel(const float* __restrict__ x, fp16* __restrict__ xo,
                             int* __restrict__ cnt,
                             const float* __restrict__ sgu, const float* __restrict__ egu,
                             const float* __restrict__ sdn, const float* __restrict__ edn,
                             fp16* __restrict__ wgu, fp16* __restrict__ wdn) {
    const int bid = blockIdx.x;
    if (bid < NA_BLOCKS) {
        if (bid == 0 && threadIdx.x < E_EXP) cnt[threadIdx.x] = 0;
        const int i4 = (bid * 256 + threadIdx.x) * 4;
        float4 v = *(const float4*)(x + i4);
        __align__(8) fp16 h[4];
        h[0] = __float2half(v.x); h[1] = __float2half(v.y);
        h[2] = __float2half(v.z); h[3] = __float2half(v.w);
        *(uint2*)(xo + i4) = *(const uint2*)h;
        return;
    }
    const int bid2 = bid - NA_BLOCKS;
    const int s = bid2 / (GUP + D_DIM);
    const int rr = bid2 - s * (GUP + D_DIM);
    if (rr < GUP) {
        const int r = rr;
        const int k4 = threadIdx.x * 4;
        const size_t dst = ((size_t)s * GUP + r) * D_DIM + k4;
        float4 v = make_float4(0.f, 0.f, 0.f, 0.f);
        if (r < GU_DIM) {
            const int sr = (r & 1) ? (r >> 1) + I_DIM : (r >> 1);
            const float* src = (s == 0) ? (sgu + (size_t)sr * D_DIM)
                                        : (egu + ((size_t)(s - 1) * GU_DIM + sr) * D_DIM);
            v = *(const float4*)(src + k4);
        }
        __align__(8) fp16 h[4];
        h[0] = __float2half(v.x); h[1] = __float2half(v.y);
        h[2] = __float2half(v.z); h[3] = __float2half(v.w);
        *(uint2*)(wgu + dst) = *(const uint2*)h;
    } else {
        if (threadIdx.x >= 240) return;
        const int n = rr - GUP;
        const int k4 = threadIdx.x * 4;
        const size_t dst = ((size_t)s * D_DIM + n) * IP + k4;
        const float* src = (s == 0) ? (sdn + (size_t)n * I_DIM)
                                    : (edn + ((size_t)(s - 1) * D_DIM + n) * I_DIM);
        __align__(8) fp16 h[4];
#pragma unroll
        for (int q = 0; q < 4; q++) {
            const int i = k4 + q;
            float v = (i < I_DIM) ? __ldg(src + i) : 0.f;
            h[q] = __float2half(v);
        }
        *(uint2*)(wdn + dst) = *(const uint2*)h;
    }
}

// ---------------- router (fp32, bit-identical routing) ----------------
__global__ void router_kernel(const float* __restrict__ x, const float* __restrict__ gw,
                              int* __restrict__ cnt, int* __restrict__ tok,
                              int4* __restrict__ tk2, float2* __restrict__ w2) {
    __shared__ float sgw[E_EXP * D_DIM];
    const int tid = threadIdx.x;
    for (int i = tid; i < E_EXP * D_DIM; i += blockDim.x) sgw[i] = gw[i];
    __syncthreads();
    const int warp = tid >> 5, lane = tid & 31;
    const int t = blockIdx.x * 8 + warp;
    const float* xt = x + (long long)t * D_DIM;
    float acc[E_EXP];
#pragma unroll
    for (int e = 0; e < E_EXP; e++) acc[e] = 0.f;
    for (int k = lane; k < D_DIM; k += 32) {
        float xv = xt[k];
#pragma unroll
        for (int e = 0; e < E_EXP; e++) acc[e] += xv * sgw[e * D_DIM + k];
    }
#pragma unroll
    for (int e = 0; e < E_EXP; e++)
#pragma unroll
        for (int off = 16; off; off >>= 1)
            acc[e] += __shfl_xor_sync(0xffffffffu, acc[e], off);
    if (lane == 0) {
        float mx = acc[0];
#pragma unroll
        for (int e = 1; e < E_EXP; e++) mx = fmaxf(mx, acc[e]);
        float p[E_EXP], Z = 0.f;
#pragma unroll
        for (int e = 0; e < E_EXP; e++) { p[e] = expf(acc[e] - mx); Z += p[e]; }
#pragma unroll
        for (int e = 0; e < E_EXP; e++) p[e] /= Z;
        int i1 = 0;
#pragma unroll
        for (int e = 1; e < E_EXP; e++) if (p[e] > p[i1]) i1 = e;
        int i2 = (i1 == 0) ? 1 : 0;
#pragma unroll
        for (int e = 0; e < E_EXP; e++) if (e != i1 && e != i2 && p[e] > p[i2]) i2 = e;
        float denom = p[i1] + p[i2] + 1e-8f;
        int pos1 = atomicAdd(&cnt[i1], 1);
        tok[i1 * T_TOKENS + pos1] = t;
        int pos2 = atomicAdd(&cnt[i2], 1);
        tok[i2 * T_TOKENS + pos2] = t;
        tk2[t] = make_int4(i1, pos1, i2, pos2);
        w2[t]  = make_float2(p[i1] / denom, p[i2] / denom);
    }
}

// ---------------- host launch ----------------
extern "C" void kernel_launch(void* const* d_in, const int* in_sizes, int n_in,
                              void* d_out, int out_size) {
    const float* x   = (const float*)d_in[0];
    const float* gw  = (const float*)d_in[1];
    const float* sgu = (const float*)d_in[2];
    const float* sdn = (const float*)d_in[3];
    const float* egu = (const float*)d_in[4];
    const float* edn = (const float*)d_in[5];
    float* out = (float*)d_out;

    cudaFuncSetAttribute(gemm_fused_kernel, cudaFuncAttributeMaxDynamicSharedMemorySize, SMEM_DYN);

    void *pCnt, *pTok, *pTk2, *pW2, *pX16, *pWgu, *pWdn;
    cudaGetSymbolAddress(&pCnt, g_cnt);
    cudaGetSymbolAddress(&pTok, g_tok);
    cudaGetSymbolAddress(&pTk2, g_tk2);
    cudaGetSymbolAddress(&pW2,  g_w2);
    cudaGetSymbolAddress(&pX16, g_x16);
    cudaGetSymbolAddress(&pWgu, g_wgu);
    cudaGetSymbolAddress(&pWdn, g_wdn);

    // #1: fused setup (cvt x, zero counters, repack both weight sets)
    setup_kernel<<<NA_BLOCKS + (GUP + D_DIM) * NSLOT, 256>>>(
        x, (fp16*)pX16, (int*)pCnt, sgu, egu, sdn, edn, (fp16*)pWgu, (fp16*)pWdn);

    // #2: router
    router_kernel<<<T_TOKENS / 8, 256>>>(x, gw, (int*)pCnt, (int*)pTok,
                                         (int4*)pTk2, (float2*)pW2);

    // #3: fused GEMM1+swiglu -> GEMM2 with per-row-band dependency flags
    gemm_fused_kernel<<<G1_BLOCKS + G2_BLOCKS, 256, SMEM_DYN>>>(out);

    // #4: combine routed contributions (atomic-free) + reset g_done flags
    combine_kernel<<<T_TOKENS, 256>>>(out);
}